// round 8
// baseline (speedup 1.0000x reference)
#include <cuda_runtime.h>
#include <cuda_fp16.h>
#include <cstdint>

// y[m,o] = scale[o]*( dot(x[m], q[o]) - zp[o]*rowsum(x[m]) ) + bias[o]
// q codes in [0,255] are EXACT in fp16 -> fp16 HMMA, fp32 accumulate.
// (tcgen05 unavailable: harness PTX target is compute_103, not 103a.)
//
// R8: persistent CTAs (grid=296, 2/SM); the 3-stage cp.async ring never
// drains -- lookahead loads cross tile boundaries, epilogue runs while the
// next tile's tiles stream in. B-fragments streamed to cut live registers.

static constexpr int M_TOTAL = 8192;    // 4*2048
static constexpr int K_TOTAL = 4096;
static constexpr int N_TOTAL = 11008;

static constexpr int BM = 128, BN = 128, BK = 64;   // BK halves = 128B rows
static constexpr int KTILES = K_TOTAL / BK;         // 64
static constexpr int STAGES = 3;
static constexpr int NUM_M = M_TOTAL / BM;          // 64
static constexpr int NUM_N = N_TOTAL / BN;          // 86
static constexpr int GROUP_M = 16;
static constexpr int NTILES = NUM_M * NUM_N;        // 5504
static constexpr int GRID   = 296;                  // 2 CTAs x 148 SMs
// 5504 = 18*296 + 176 -> first 176 CTAs do 19 tiles, rest 18.
static constexpr int REM    = NTILES - (NTILES / GRID) * GRID;  // 176

static constexpr int A_STAGE = BM * BK;             // halves
static constexpr int STAGE_H = (BM + BN) * BK;      // 16384 halves = 32KB
static constexpr int SMEM_BYTES = STAGES * STAGE_H * 2;  // 96KB -> 2 CTAs/SM

// Scratch (static __device__ arrays: allocation-free per harness rules)
__device__ __half g_Xh[(size_t)M_TOTAL * K_TOTAL];
__device__ __half g_Wh[(size_t)N_TOTAL * K_TOTAL];
__device__ float  g_rowsum[M_TOTAL];

// ---------------------------------------------------------------------------
__device__ __forceinline__ int swz(int row, int chunk) {
    // 128B rows, 8x16B chunks, xor swizzle -> conflict-free ldmatrix/cp.async
    return row * BK + ((chunk ^ (row & 7)) << 3);
}
__device__ __forceinline__ void cp_async16(void* s, const void* g) {
    uint32_t sa = (uint32_t)__cvta_generic_to_shared(s);
    asm volatile("cp.async.cg.shared.global [%0], [%1], 16;" :: "r"(sa), "l"(g));
}
__device__ __forceinline__ void cp_commit() { asm volatile("cp.async.commit_group;"); }

__device__ __forceinline__ void ldm_x4(uint32_t* r, const __half* p) {
    uint32_t sa = (uint32_t)__cvta_generic_to_shared(p);
    asm volatile("ldmatrix.sync.aligned.m8n8.x4.shared.b16 {%0,%1,%2,%3}, [%4];"
                 : "=r"(r[0]), "=r"(r[1]), "=r"(r[2]), "=r"(r[3]) : "r"(sa));
}
__device__ __forceinline__ void mma16816(float* c, const uint32_t* a, const uint32_t* b) {
    asm volatile(
        "mma.sync.aligned.m16n8k16.row.col.f32.f16.f16.f32 "
        "{%0,%1,%2,%3}, {%4,%5,%6,%7}, {%8,%9}, {%0,%1,%2,%3};"
        : "+f"(c[0]), "+f"(c[1]), "+f"(c[2]), "+f"(c[3])
        : "r"(a[0]), "r"(a[1]), "r"(a[2]), "r"(a[3]), "r"(b[0]), "r"(b[1]));
}

// ---------------------------------------------------------------------------
// fused conversion: blocks [0,8192) do x rows (+rowsum); rest convert W.
// ---------------------------------------------------------------------------
__global__ void convert_fused_kernel(const float* __restrict__ x,
                                     const int* __restrict__ q) {
    if (blockIdx.x < M_TOTAL) {
        const int row = blockIdx.x;
        const float* xr = x + (size_t)row * K_TOTAL;
        __half* xo = g_Xh + (size_t)row * K_TOTAL;
        float s = 0.f;
        for (int i = threadIdx.x * 4; i < K_TOTAL; i += blockDim.x * 4) {
            float4 v = *(const float4*)(xr + i);
            s += v.x + v.y + v.z + v.w;
            *(__half2*)(xo + i)     = __floats2half2_rn(v.x, v.y);
            *(__half2*)(xo + i + 2) = __floats2half2_rn(v.z, v.w);
        }
        #pragma unroll
        for (int off = 16; off; off >>= 1) s += __shfl_down_sync(~0u, s, off);
        __shared__ float ws[8];
        if ((threadIdx.x & 31) == 0) ws[threadIdx.x >> 5] = s;
        __syncthreads();
        if (threadIdx.x < 8) {
            float v = ws[threadIdx.x];
            #pragma unroll
            for (int off = 4; off; off >>= 1) v += __shfl_down_sync(0xffu, v, off);
            if (threadIdx.x == 0) g_rowsum[row] = v;
        }
    } else {
        const size_t total4 = (size_t)N_TOTAL * K_TOTAL / 4;
        const size_t stride = (size_t)(gridDim.x - M_TOTAL) * blockDim.x;
        for (size_t i = (size_t)(blockIdx.x - M_TOTAL) * blockDim.x + threadIdx.x;
             i < total4; i += stride) {
            int4 v = ((const int4*)q)[i];
            __half2* o = (__half2*)(g_Wh + i * 4);
            o[0] = __halves2half2(__int2half_rn(v.x), __int2half_rn(v.y));
            o[1] = __halves2half2(__int2half_rn(v.z), __int2half_rn(v.w));
        }
    }
}

// ---------------------------------------------------------------------------
// Persistent GEMM: 128x128x64 CTA tile, 8 warps (4m x 2n), warp tile 32x64.
// One flat loop over (tile, ktile); ring never drains across tiles.
// ---------------------------------------------------------------------------
__global__ void __launch_bounds__(256, 2) woq_gemm_kernel(
    const float* __restrict__ scales, const float* __restrict__ zps,
    const float* __restrict__ bias, float* __restrict__ out)
{
    extern __shared__ __half smem[];

    const int tid  = threadIdx.x;
    const int lane = tid & 31;
    const int warp = tid >> 5;
    const int wm = warp & 3;   // 0..3 -> 32 rows each
    const int wn = warp >> 2;  // 0..1 -> 64 cols each
    const int bid = blockIdx.x;

    const int myTiles = (bid < REM) ? (NTILES / GRID + 1) : (NTILES / GRID);
    const int JTOT = myTiles * KTILES;

    // grouped-M raster decode (tile id -> bm, bn)
    auto decode = [&](int t, int& bm_, int& bn_) {
        const int g = t / (GROUP_M * NUM_N);
        const int r = t % (GROUP_M * NUM_N);
        bm_ = (g * GROUP_M + (r % GROUP_M)) * BM;
        bn_ = (r / GROUP_M) * BN;
    };

    // loader thread mapping: thread t -> row t/8 (+32 per pass), chunk t%8
    const int lrow   = tid >> 3;   // 0..31
    const int lchunk = tid & 7;    // 0..7

    int bm_l, bn_l;                 // tile coords for the LOAD stream
    decode(bid, bm_l, bn_l);

    auto load_stage = [&](int s, int lkt) {
        __half* sa = smem + s * STAGE_H;
        __half* sb = sa + A_STAGE;
        const __half* ga = g_Xh + (size_t)(bm_l + lrow) * K_TOTAL + lkt * BK + lchunk * 8;
        const __half* gb = g_Wh + (size_t)(bn_l + lrow) * K_TOTAL + lkt * BK + lchunk * 8;
        #pragma unroll
        for (int p = 0; p < 4; p++) {
            cp_async16(sa + swz(lrow + p * 32, lchunk), ga + (size_t)(p * 32) * K_TOTAL);
            cp_async16(sb + swz(lrow + p * 32, lchunk), gb + (size_t)(p * 32) * K_TOTAL);
        }
    };

    float c[2][8][4];
    #pragma unroll
    for (int i = 0; i < 2; i++)
        #pragma unroll
        for (int j = 0; j < 8; j++)
            #pragma unroll
            for (int k = 0; k < 4; k++) c[i][j][k] = 0.f;

    // ldmatrix lane addressing
    const int mat    = lane >> 3;
    const int arow0  = wm * 32 + (mat & 1) * 8 + (lane & 7);     // + mi*16
    const int achunk = mat >> 1;                                  // + kc
    const int brow0  = wn * 64 + ((mat >> 1) << 3) + (lane & 7);  // + nj*16
    const int bchunk = mat & 1;                                   // + kc

    // epilogue lane addressing
    const int er = lane >> 2;        // row within 8
    const int ec = (lane & 3) * 2;   // col pair within 8

    // prologue: fill 2 stages (only cold fill in the whole kernel)
    load_stage(0, 0); cp_commit();
    load_stage(1, 1); cp_commit();

    int bm = bm_l, bn = bn_l;        // current COMPUTE tile coords
    int tileslot = 0;

    for (int j = 0; j < JTOT; j++) {
        const int kt = j & (KTILES - 1);
        asm volatile("cp.async.wait_group 1;");
        __syncthreads();

        const int nk = j + 2;
        if (nk < JTOT) {
            const int lkt = nk & (KTILES - 1);
            if (lkt == 0) decode(bid + (nk >> 6) * GRID, bm_l, bn_l);
            load_stage(nk % STAGES, lkt);
        }
        cp_commit();   // always commit so group counting stays exact

        // MMA on stage j%3; B fragments streamed (1 ldmatrix -> 4 MMAs)
        {
            const __half* sa = smem + (j % STAGES) * STAGE_H;
            const __half* sb = sa + A_STAGE;
            #pragma unroll
            for (int kk = 0; kk < 4; kk++) {
                const int kc = kk << 1;
                uint32_t a[2][4];
                #pragma unroll
                for (int mi = 0; mi < 2; mi++)
                    ldm_x4(a[mi], sa + swz(arow0 + mi * 16, kc + achunk));
                #pragma unroll
                for (int nj = 0; nj < 4; nj++) {
                    uint32_t t[4];
                    ldm_x4(t, sb + swz(brow0 + nj * 16, kc + bchunk));
                    mma16816(c[0][nj*2  ], a[0], t);
                    mma16816(c[0][nj*2+1], a[0], t + 2);
                    mma16816(c[1][nj*2  ], a[1], t);
                    mma16816(c[1][nj*2+1], a[1], t + 2);
                }
            }
        }

        if (kt == KTILES - 1) {
            // epilogue for tile (bm, bn); ring keeps streaming underneath
            float rs[2][2];
            #pragma unroll
            for (int mi = 0; mi < 2; mi++)
                #pragma unroll
                for (int h = 0; h < 2; h++)
                    rs[mi][h] = g_rowsum[bm + wm*32 + mi*16 + h*8 + er];

            #pragma unroll
            for (int nt = 0; nt < 8; nt++) {
                const int gn = bn + wn*64 + nt*8 + ec;
                const float s0 = scales[gn],  s1 = scales[gn+1];
                const float z0 = zps[gn],     z1 = zps[gn+1];
                const float b0 = bias[gn],    b1 = bias[gn+1];
                #pragma unroll
                for (int mi = 0; mi < 2; mi++) {
                    #pragma unroll
                    for (int h = 0; h < 2; h++) {
                        const int gm = bm + wm*32 + mi*16 + h*8 + er;
                        float2 v;
                        v.x = s0 * (c[mi][nt][h*2+0] - z0 * rs[mi][h]) + b0;
                        v.y = s1 * (c[mi][nt][h*2+1] - z1 * rs[mi][h]) + b1;
                        *(float2*)(out + (size_t)gm * N_TOTAL + gn) = v;
                        c[mi][nt][h*2+0] = 0.f;   // reset for next tile
                        c[mi][nt][h*2+1] = 0.f;
                    }
                }
            }
            // advance compute tile: bm_l/bn_l were decoded for the next tile
            // at iteration j-1 (when its lkt hit 0), so they're current here.
            tileslot++;
            if (tileslot < myTiles) { bm = bm_l; bn = bn_l; }
        }
    }
}

// ---------------------------------------------------------------------------
extern "C" void kernel_launch(void* const* d_in, const int* in_sizes, int n_in,
                              void* d_out, int out_size) {
    const float* x  = (const float*)d_in[0];
    const int*   qw = (const int*)d_in[1];
    const float* sc = (const float*)d_in[2];
    const float* zp = (const float*)d_in[3];
    const float* bi = (const float*)d_in[4];
    float* out = (float*)d_out;

    convert_fused_kernel<<<M_TOTAL + 8192, 256>>>(x, qw);

    cudaFuncSetAttribute(woq_gemm_kernel,
                         cudaFuncAttributeMaxDynamicSharedMemorySize, SMEM_BYTES);
    woq_gemm_kernel<<<GRID, 256, SMEM_BYTES>>>(sc, zp, bi, out);
}

// round 9
// speedup vs baseline: 1.1025x; 1.1025x over previous
#include <cuda_runtime.h>
#include <cuda_fp16.h>
#include <cstdint>

// y[m,o] = scale[o]*( dot(x[m], q[o]) - zp[o]*rowsum(x[m]) ) + bias[o]
// q codes in [0,255] are EXACT in fp16 -> fp16 HMMA, fp32 accumulate.
// (tcgen05 unavailable: harness PTX target is compute_103, not 103a.)
//
// R8 post-mortem: persistent rewrite regressed (tensor 77->67). This round:
// R7 structure verbatim + cross-barrier A-fragment prefetch (stage kt+1 is
// provably visible at the bottom of iteration kt) + kc/nj fragment double
// buffering at IDENTICAL register cost (24 frag regs either way).

static constexpr int M_TOTAL = 8192;    // 4*2048
static constexpr int K_TOTAL = 4096;
static constexpr int N_TOTAL = 11008;

static constexpr int BM = 128, BN = 128, BK = 64;   // BK halves = 128B rows
static constexpr int KTILES = K_TOTAL / BK;         // 64
static constexpr int STAGES = 3;
static constexpr int NUM_M = M_TOTAL / BM;          // 64
static constexpr int NUM_N = N_TOTAL / BN;          // 86
static constexpr int GROUP_M = 16;

static constexpr int A_STAGE = BM * BK;             // halves
static constexpr int STAGE_H = (BM + BN) * BK;      // 16384 halves = 32KB
static constexpr int SMEM_BYTES = STAGES * STAGE_H * 2;  // 96KB -> 2 CTAs/SM

// Scratch (static __device__ arrays: allocation-free per harness rules)
__device__ __half g_Xh[(size_t)M_TOTAL * K_TOTAL];
__device__ __half g_Wh[(size_t)N_TOTAL * K_TOTAL];
__device__ float  g_rowsum[M_TOTAL];

// ---------------------------------------------------------------------------
__device__ __forceinline__ int swz(int row, int chunk) {
    // 128B rows, 8x16B chunks, xor swizzle -> conflict-free ldmatrix/cp.async
    return row * BK + ((chunk ^ (row & 7)) << 3);
}
__device__ __forceinline__ void cp_async16(void* s, const void* g) {
    uint32_t sa = (uint32_t)__cvta_generic_to_shared(s);
    asm volatile("cp.async.cg.shared.global [%0], [%1], 16;" :: "r"(sa), "l"(g));
}
__device__ __forceinline__ void cp_commit() { asm volatile("cp.async.commit_group;"); }

__device__ __forceinline__ void ldm_x4(uint32_t* r, const __half* p) {
    uint32_t sa = (uint32_t)__cvta_generic_to_shared(p);
    asm volatile("ldmatrix.sync.aligned.m8n8.x4.shared.b16 {%0,%1,%2,%3}, [%4];"
                 : "=r"(r[0]), "=r"(r[1]), "=r"(r[2]), "=r"(r[3]) : "r"(sa));
}
__device__ __forceinline__ void mma16816(float* c, const uint32_t* a, const uint32_t* b) {
    asm volatile(
        "mma.sync.aligned.m16n8k16.row.col.f32.f16.f16.f32 "
        "{%0,%1,%2,%3}, {%4,%5,%6,%7}, {%8,%9}, {%0,%1,%2,%3};"
        : "+f"(c[0]), "+f"(c[1]), "+f"(c[2]), "+f"(c[3])
        : "r"(a[0]), "r"(a[1]), "r"(a[2]), "r"(a[3]), "r"(b[0]), "r"(b[1]));
}

// ---------------------------------------------------------------------------
// fused conversion: blocks [0,8192) do x rows (+rowsum); rest convert W.
// ---------------------------------------------------------------------------
__global__ void convert_fused_kernel(const float* __restrict__ x,
                                     const int* __restrict__ q) {
    if (blockIdx.x < M_TOTAL) {
        const int row = blockIdx.x;
        const float* xr = x + (size_t)row * K_TOTAL;
        __half* xo = g_Xh + (size_t)row * K_TOTAL;
        float s = 0.f;
        for (int i = threadIdx.x * 4; i < K_TOTAL; i += blockDim.x * 4) {
            float4 v = *(const float4*)(xr + i);
            s += v.x + v.y + v.z + v.w;
            *(__half2*)(xo + i)     = __floats2half2_rn(v.x, v.y);
            *(__half2*)(xo + i + 2) = __floats2half2_rn(v.z, v.w);
        }
        #pragma unroll
        for (int off = 16; off; off >>= 1) s += __shfl_down_sync(~0u, s, off);
        __shared__ float ws[8];
        if ((threadIdx.x & 31) == 0) ws[threadIdx.x >> 5] = s;
        __syncthreads();
        if (threadIdx.x < 8) {
            float v = ws[threadIdx.x];
            #pragma unroll
            for (int off = 4; off; off >>= 1) v += __shfl_down_sync(0xffu, v, off);
            if (threadIdx.x == 0) g_rowsum[row] = v;
        }
    } else {
        const size_t total4 = (size_t)N_TOTAL * K_TOTAL / 4;
        const size_t stride = (size_t)(gridDim.x - M_TOTAL) * blockDim.x;
        for (size_t i = (size_t)(blockIdx.x - M_TOTAL) * blockDim.x + threadIdx.x;
             i < total4; i += stride) {
            int4 v = ((const int4*)q)[i];
            __half2* o = (__half2*)(g_Wh + i * 4);
            o[0] = __halves2half2(__int2half_rn(v.x), __int2half_rn(v.y));
            o[1] = __halves2half2(__int2half_rn(v.z), __int2half_rn(v.w));
        }
    }
}

// ---------------------------------------------------------------------------
// GEMM: 128x128x64 CTA tile, 8 warps (4m x 2n) -> warp tile 32x64,
// 3-stage cp.async ring (wait_group 1), grouped-M raster, 2 CTAs/SM.
// Fragment pipeline: A double-buffered across kc AND across the barrier
// (next tile's kc=0 A-frags prefetched pre-barrier); B double-buffered
// across nj (one LDSM group in flight ahead of the MMA burst).
// ---------------------------------------------------------------------------
__global__ void __launch_bounds__(256, 2) woq_gemm_kernel(
    const float* __restrict__ scales, const float* __restrict__ zps,
    const float* __restrict__ bias, float* __restrict__ out)
{
    extern __shared__ __half smem[];

    const int tid  = threadIdx.x;
    const int lane = tid & 31;
    const int warp = tid >> 5;
    const int wm = warp & 3;   // 0..3 -> 32 rows each
    const int wn = warp >> 2;  // 0..1 -> 64 cols each

    // grouped-M rasterization -> L2-resident wave working set
    const int bid = blockIdx.x;
    const int g   = bid / (GROUP_M * NUM_N);
    const int r   = bid % (GROUP_M * NUM_N);
    const int bm  = (g * GROUP_M + (r % GROUP_M)) * BM;
    const int bn  = (r / GROUP_M) * BN;

    // Coalesced loaders: thread t -> row t/8 (+32 per pass), 16B chunk t%8.
    const int lrow   = tid >> 3;   // 0..31
    const int lchunk = tid & 7;    // 0..7
    const __half* gA = g_Xh + (size_t)(bm + lrow) * K_TOTAL + lchunk * 8;
    const __half* gB = g_Wh + (size_t)(bn + lrow) * K_TOTAL + lchunk * 8;

    auto load_stage = [&](int s, int kt) {
        __half* sa = smem + s * STAGE_H;
        __half* sb = sa + A_STAGE;
        const __half* ga = gA + kt * BK;
        const __half* gb = gB + kt * BK;
        #pragma unroll
        for (int p = 0; p < 4; p++) {
            cp_async16(sa + swz(lrow + p * 32, lchunk), ga + (size_t)(p * 32) * K_TOTAL);
            cp_async16(sb + swz(lrow + p * 32, lchunk), gb + (size_t)(p * 32) * K_TOTAL);
        }
    };

    float c[2][8][4];
    #pragma unroll
    for (int i = 0; i < 2; i++)
        #pragma unroll
        for (int j = 0; j < 8; j++)
            #pragma unroll
            for (int k = 0; k < 4; k++) c[i][j][k] = 0.f;

    // ldmatrix lane addressing
    const int mat    = lane >> 3;
    const int arow0  = wm * 32 + (mat & 1) * 8 + (lane & 7);     // + mi*16
    const int achunk = mat >> 1;                                  // + kc
    const int brow0  = wn * 64 + ((mat >> 1) << 3) + (lane & 7);  // + nj*16
    const int bchunk = mat & 1;                                   // + kc

    // prologue: 2 stages in flight
    #pragma unroll
    for (int s = 0; s < STAGES - 1; s++) { load_stage(s, s); cp_commit(); }

    // A fragments, double-buffered by kc parity. a[0] must hold the kc=0
    // fragments of the CURRENT tile at the top of each iteration.
    uint32_t a[2][2][4];

    for (int kt = 0; kt < KTILES; kt++) {
        const int cur = kt % STAGES;
        asm volatile("cp.async.wait_group %0;" :: "n"(STAGES - 2));
        __syncthreads();

        const int nk = kt + STAGES - 1;
        if (nk < KTILES) load_stage(nk % STAGES, nk);
        cp_commit();   // always commit so group counting stays exact

        const __half* sa = smem + cur * STAGE_H;
        const __half* sb = sa + A_STAGE;

        if (kt == 0) {   // only cold A-fragment load in the kernel
            ldm_x4(a[0][0], sa + swz(arow0,      achunk));
            ldm_x4(a[0][1], sa + swz(arow0 + 16, achunk));
        }

        #pragma unroll
        for (int kk = 0; kk < 4; kk++) {
            const int kc  = kk << 1;
            const int pc  = kk & 1;         // current A buffer
            uint32_t b[2][4];

            // first B group for this kc
            ldm_x4(b[0], sb + swz(brow0, kc + bchunk));
            // prefetch next kc's A fragments (overlaps with MMAs below)
            if (kk < 3) {
                ldm_x4(a[pc ^ 1][0], sa + swz(arow0,      kc + 2 + achunk));
                ldm_x4(a[pc ^ 1][1], sa + swz(arow0 + 16, kc + 2 + achunk));
            }

            #pragma unroll
            for (int nj = 0; nj < 4; nj++) {
                const int pb = nj & 1;
                if (nj < 3)
                    ldm_x4(b[pb ^ 1], sb + swz(brow0 + (nj + 1) * 16, kc + bchunk));
                mma16816(c[0][nj*2  ], a[pc][0], b[pb]);
                mma16816(c[0][nj*2+1], a[pc][0], b[pb] + 2);
                mma16816(c[1][nj*2  ], a[pc][1], b[pb]);
                mma16816(c[1][nj*2+1], a[pc][1], b[pb] + 2);
            }
        }

        // Cross-barrier prefetch: stage (kt+1)%3 was published by THIS
        // iteration's barrier (its cp.async waited at this wait_group) and
        // is not overwritten until iteration kt+2 -> safe to read here.
        if (kt + 1 < KTILES) {
            const __half* sn = smem + ((kt + 1) % STAGES) * STAGE_H;
            ldm_x4(a[0][0], sn + swz(arow0,      achunk));
            ldm_x4(a[0][1], sn + swz(arow0 + 16, achunk));
        }
    }

    // epilogue: y = s*(acc - zp*rowsum) + bias
    const int er = lane >> 2;        // row within 8
    const int ec = (lane & 3) * 2;   // col pair within 8

    float rs[2][2];
    #pragma unroll
    for (int mi = 0; mi < 2; mi++)
        #pragma unroll
        for (int h = 0; h < 2; h++)
            rs[mi][h] = g_rowsum[bm + wm*32 + mi*16 + h*8 + er];

    #pragma unroll
    for (int nt = 0; nt < 8; nt++) {
        const int gn = bn + wn*64 + nt*8 + ec;
        const float s0 = scales[gn],  s1 = scales[gn+1];
        const float z0 = zps[gn],     z1 = zps[gn+1];
        const float b0 = bias[gn],    b1 = bias[gn+1];
        #pragma unroll
        for (int mi = 0; mi < 2; mi++) {
            #pragma unroll
            for (int h = 0; h < 2; h++) {
                const int gm = bm + wm*32 + mi*16 + h*8 + er;
                float2 v;
                v.x = s0 * (c[mi][nt][h*2+0] - z0 * rs[mi][h]) + b0;
                v.y = s1 * (c[mi][nt][h*2+1] - z1 * rs[mi][h]) + b1;
                *(float2*)(out + (size_t)gm * N_TOTAL + gn) = v;
            }
        }
    }
}

// ---------------------------------------------------------------------------
extern "C" void kernel_launch(void* const* d_in, const int* in_sizes, int n_in,
                              void* d_out, int out_size) {
    const float* x  = (const float*)d_in[0];
    const int*   qw = (const int*)d_in[1];
    const float* sc = (const float*)d_in[2];
    const float* zp = (const float*)d_in[3];
    const float* bi = (const float*)d_in[4];
    float* out = (float*)d_out;

    convert_fused_kernel<<<M_TOTAL + 8192, 256>>>(x, qw);

    cudaFuncSetAttribute(woq_gemm_kernel,
                         cudaFuncAttributeMaxDynamicSharedMemorySize, SMEM_BYTES);
    woq_gemm_kernel<<<NUM_M * NUM_N, 256, SMEM_BYTES>>>(sc, zp, bi, out);
}

// round 10
// speedup vs baseline: 1.2173x; 1.1041x over previous
#include <cuda_runtime.h>
#include <cuda_fp16.h>
#include <cstdint>

// y[m,o] = scale[o]*( dot(x[m], q[o]) - zp[o]*rowsum(x[m]) ) + bias[o]
// q codes in [0,255] are EXACT in fp16 -> fp16 HMMA, fp32 accumulate.
// (tcgen05 unavailable: harness PTX target is compute_103, not 103a.)
//
// R8/R9 post-mortem: every inner-loop restructuring loses to ptxas's own
// schedule of the R7 body. This round keeps R7 byte-for-byte EXCEPT:
//  - K-loop unrolled by STAGES=3 -> all stage indices compile-time, smem
//    addresses become base+const (kills the %3 IMAD chains, ALU 13% -> ~8%)
//  - rowsum LDGs hoisted above the K-loop (off the epilogue tail)

static constexpr int M_TOTAL = 8192;    // 4*2048
static constexpr int K_TOTAL = 4096;
static constexpr int N_TOTAL = 11008;

static constexpr int BM = 128, BN = 128, BK = 64;   // BK halves = 128B rows
static constexpr int KTILES = K_TOTAL / BK;         // 64
static constexpr int STAGES = 3;
static constexpr int NUM_M = M_TOTAL / BM;          // 64
static constexpr int NUM_N = N_TOTAL / BN;          // 86
static constexpr int GROUP_M = 16;

static constexpr int A_STAGE = BM * BK;             // halves
static constexpr int STAGE_H = (BM + BN) * BK;      // 16384 halves = 32KB
static constexpr int SMEM_BYTES = STAGES * STAGE_H * 2;  // 96KB -> 2 CTAs/SM

// Scratch (static __device__ arrays: allocation-free per harness rules)
__device__ __half g_Xh[(size_t)M_TOTAL * K_TOTAL];
__device__ __half g_Wh[(size_t)N_TOTAL * K_TOTAL];
__device__ float  g_rowsum[M_TOTAL];

// ---------------------------------------------------------------------------
__device__ __forceinline__ int swz(int row, int chunk) {
    // 128B rows, 8x16B chunks, xor swizzle -> conflict-free ldmatrix/cp.async
    return row * BK + ((chunk ^ (row & 7)) << 3);
}
__device__ __forceinline__ void cp_async16(void* s, const void* g) {
    uint32_t sa = (uint32_t)__cvta_generic_to_shared(s);
    asm volatile("cp.async.cg.shared.global [%0], [%1], 16;" :: "r"(sa), "l"(g));
}
__device__ __forceinline__ void cp_commit() { asm volatile("cp.async.commit_group;"); }

__device__ __forceinline__ void ldm_x4(uint32_t* r, const __half* p) {
    uint32_t sa = (uint32_t)__cvta_generic_to_shared(p);
    asm volatile("ldmatrix.sync.aligned.m8n8.x4.shared.b16 {%0,%1,%2,%3}, [%4];"
                 : "=r"(r[0]), "=r"(r[1]), "=r"(r[2]), "=r"(r[3]) : "r"(sa));
}
__device__ __forceinline__ void mma16816(float* c, const uint32_t* a, const uint32_t* b) {
    asm volatile(
        "mma.sync.aligned.m16n8k16.row.col.f32.f16.f16.f32 "
        "{%0,%1,%2,%3}, {%4,%5,%6,%7}, {%8,%9}, {%0,%1,%2,%3};"
        : "+f"(c[0]), "+f"(c[1]), "+f"(c[2]), "+f"(c[3])
        : "r"(a[0]), "r"(a[1]), "r"(a[2]), "r"(a[3]), "r"(b[0]), "r"(b[1]));
}

// ---------------------------------------------------------------------------
// fused conversion: blocks [0,8192) do x rows (+rowsum); rest convert W.
// ---------------------------------------------------------------------------
__global__ void convert_fused_kernel(const float* __restrict__ x,
                                     const int* __restrict__ q) {
    if (blockIdx.x < M_TOTAL) {
        const int row = blockIdx.x;
        const float* xr = x + (size_t)row * K_TOTAL;
        __half* xo = g_Xh + (size_t)row * K_TOTAL;
        float s = 0.f;
        for (int i = threadIdx.x * 4; i < K_TOTAL; i += blockDim.x * 4) {
            float4 v = *(const float4*)(xr + i);
            s += v.x + v.y + v.z + v.w;
            *(__half2*)(xo + i)     = __floats2half2_rn(v.x, v.y);
            *(__half2*)(xo + i + 2) = __floats2half2_rn(v.z, v.w);
        }
        #pragma unroll
        for (int off = 16; off; off >>= 1) s += __shfl_down_sync(~0u, s, off);
        __shared__ float ws[8];
        if ((threadIdx.x & 31) == 0) ws[threadIdx.x >> 5] = s;
        __syncthreads();
        if (threadIdx.x < 8) {
            float v = ws[threadIdx.x];
            #pragma unroll
            for (int off = 4; off; off >>= 1) v += __shfl_down_sync(0xffu, v, off);
            if (threadIdx.x == 0) g_rowsum[row] = v;
        }
    } else {
        const size_t total4 = (size_t)N_TOTAL * K_TOTAL / 4;
        const size_t stride = (size_t)(gridDim.x - M_TOTAL) * blockDim.x;
        for (size_t i = (size_t)(blockIdx.x - M_TOTAL) * blockDim.x + threadIdx.x;
             i < total4; i += stride) {
            int4 v = ((const int4*)q)[i];
            __half2* o = (__half2*)(g_Wh + i * 4);
            o[0] = __halves2half2(__int2half_rn(v.x), __int2half_rn(v.y));
            o[1] = __halves2half2(__int2half_rn(v.z), __int2half_rn(v.w));
        }
    }
}

// ---------------------------------------------------------------------------
// GEMM: 128x128x64 CTA tile, 8 warps (4m x 2n) -> warp tile 32x64,
// 3-stage cp.async ring (wait_group 1), grouped-M raster, 2 CTAs/SM.
// K-loop unrolled by 3: all stage indices are compile-time constants.
// ---------------------------------------------------------------------------
__global__ void __launch_bounds__(256, 2) woq_gemm_kernel(
    const float* __restrict__ scales, const float* __restrict__ zps,
    const float* __restrict__ bias, float* __restrict__ out)
{
    extern __shared__ __half smem[];

    const int tid  = threadIdx.x;
    const int lane = tid & 31;
    const int warp = tid >> 5;
    const int wm = warp & 3;   // 0..3 -> 32 rows each
    const int wn = warp >> 2;  // 0..1 -> 64 cols each

    // grouped-M rasterization -> L2-resident wave working set
    const int bid = blockIdx.x;
    const int g   = bid / (GROUP_M * NUM_N);
    const int r   = bid % (GROUP_M * NUM_N);
    const int bm  = (g * GROUP_M + (r % GROUP_M)) * BM;
    const int bn  = (r / GROUP_M) * BN;

    // Coalesced loaders: thread t -> row t/8 (+32 per pass), 16B chunk t%8.
    const int lrow   = tid >> 3;   // 0..31
    const int lchunk = tid & 7;    // 0..7
    const __half* gA = g_Xh + (size_t)(bm + lrow) * K_TOTAL + lchunk * 8;
    const __half* gB = g_Wh + (size_t)(bn + lrow) * K_TOTAL + lchunk * 8;

    auto load_stage = [&](int s, int kt) {
        __half* sa = smem + s * STAGE_H;    // s is a literal at every call site
        __half* sb = sa + A_STAGE;
        const __half* ga = gA + kt * BK;
        const __half* gb = gB + kt * BK;
        #pragma unroll
        for (int p = 0; p < 4; p++) {
            cp_async16(sa + swz(lrow + p * 32, lchunk), ga + (size_t)(p * 32) * K_TOTAL);
            cp_async16(sb + swz(lrow + p * 32, lchunk), gb + (size_t)(p * 32) * K_TOTAL);
        }
    };

    float c[2][8][4];
    #pragma unroll
    for (int i = 0; i < 2; i++)
        #pragma unroll
        for (int j = 0; j < 8; j++)
            #pragma unroll
            for (int k = 0; k < 4; k++) c[i][j][k] = 0.f;

    // ldmatrix lane addressing
    const int mat    = lane >> 3;
    const int arow0  = wm * 32 + (mat & 1) * 8 + (lane & 7);     // + mi*16
    const int achunk = mat >> 1;                                  // + kc
    const int brow0  = wn * 64 + ((mat >> 1) << 3) + (lane & 7);  // + nj*16
    const int bchunk = mat & 1;                                   // + kc

    // epilogue lane addressing + rowsum prefetch (off the tail path)
    const int er = lane >> 2;        // row within 8
    const int ec = (lane & 3) * 2;   // col pair within 8
    float rs[2][2];
    #pragma unroll
    for (int mi = 0; mi < 2; mi++)
        #pragma unroll
        for (int h = 0; h < 2; h++)
            rs[mi][h] = g_rowsum[bm + wm*32 + mi*16 + h*8 + er];

    // one pipeline iteration; `cur` is a compile-time literal at each call
    auto k_iter = [&](int kt, const int cur) {
        asm volatile("cp.async.wait_group 1;");
        __syncthreads();

        const int nk = kt + STAGES - 1;
        const int nstage = (cur + 2 >= STAGES) ? cur - 1 : cur + 2;  // literal
        if (nk < KTILES) load_stage(nstage, nk);
        cp_commit();   // always commit so group counting stays exact

        const __half* sa = smem + cur * STAGE_H;
        const __half* sb = sa + A_STAGE;

        #pragma unroll
        for (int kk = 0; kk < 4; kk++) {
            const int kc = kk << 1;
            uint32_t a[2][4];
            #pragma unroll
            for (int mi = 0; mi < 2; mi++)
                ldm_x4(a[mi], sa + swz(arow0 + mi * 16, kc + achunk));
            uint32_t b[8][2];
            #pragma unroll
            for (int nj = 0; nj < 4; nj++) {
                uint32_t t[4];
                ldm_x4(t, sb + swz(brow0 + nj * 16, kc + bchunk));
                b[nj*2  ][0] = t[0]; b[nj*2  ][1] = t[1];
                b[nj*2+1][0] = t[2]; b[nj*2+1][1] = t[3];
            }
            #pragma unroll
            for (int mi = 0; mi < 2; mi++)
                #pragma unroll
                for (int nt = 0; nt < 8; nt++)
                    mma16816(c[mi][nt], a[mi], b[nt]);
        }
    };

    // prologue: 2 stages in flight
    load_stage(0, 0); cp_commit();
    load_stage(1, 1); cp_commit();

    // 64 iterations = 21 full triples + 1 (63 % 3 == 0)
    int kt = 0;
    #pragma unroll 1
    for (int t3 = 0; t3 < KTILES / 3; t3++) {   // 21 triples -> kt 0..62
        k_iter(kt + 0, 0);
        k_iter(kt + 1, 1);
        k_iter(kt + 2, 2);
        kt += 3;
    }
    k_iter(63, 0);                               // final iteration, stage 0

    // epilogue: y = s*(acc - zp*rowsum) + bias
    #pragma unroll
    for (int nt = 0; nt < 8; nt++) {
        const int gn = bn + wn*64 + nt*8 + ec;
        const float s0 = scales[gn],  s1 = scales[gn+1];
        const float z0 = zps[gn],     z1 = zps[gn+1];
        const float b0 = bias[gn],    b1 = bias[gn+1];
        #pragma unroll
        for (int mi = 0; mi < 2; mi++) {
            #pragma unroll
            for (int h = 0; h < 2; h++) {
                const int gm = bm + wm*32 + mi*16 + h*8 + er;
                float2 v;
                v.x = s0 * (c[mi][nt][h*2+0] - z0 * rs[mi][h]) + b0;
                v.y = s1 * (c[mi][nt][h*2+1] - z1 * rs[mi][h]) + b1;
                *(float2*)(out + (size_t)gm * N_TOTAL + gn) = v;
            }
        }
    }
}

// ---------------------------------------------------------------------------
extern "C" void kernel_launch(void* const* d_in, const int* in_sizes, int n_in,
                              void* d_out, int out_size) {
    const float* x  = (const float*)d_in[0];
    const int*   qw = (const int*)d_in[1];
    const float* sc = (const float*)d_in[2];
    const float* zp = (const float*)d_in[3];
    const float* bi = (const float*)d_in[4];
    float* out = (float*)d_out;

    convert_fused_kernel<<<M_TOTAL + 8192, 256>>>(x, qw);

    cudaFuncSetAttribute(woq_gemm_kernel,
                         cudaFuncAttributeMaxDynamicSharedMemorySize, SMEM_BYTES);
    woq_gemm_kernel<<<NUM_M * NUM_N, 256, SMEM_BYTES>>>(sc, zp, bi, out);
}